// round 16
// baseline (speedup 1.0000x reference)
#include <cuda_runtime.h>

#define NQ 13
#define FULL 0xffffffffu

// One transfer step (verified R5-R15): v_new = L(v) given wire params.
__device__ __forceinline__ void tstep(
    float i00, float i11, float i01x, float i01y,
    float g0x, float g0y, float g1x, float g1y,
    float gm, float gux, float guy,
    float& o00, float& o11, float& o01x, float& o01y)
{
    const float h00x = fmaf(g0x, i00, fmaf(g1x, i01x, -g1y * i01y));
    const float h00y = fmaf(g0y, i00, fmaf(g1x, i01y,  g1y * i01x));
    const float h01x = fmaf(g1x, i00, fmaf(g0x, i01x, -g0y * i01y));
    const float h01y = fmaf(g1y, i00, fmaf(g0x, i01y,  g0y * i01x));
    const float h10x = fmaf(g1x, i11, fmaf(g0x, i01x,  g0y * i01y));
    const float h10y = fmaf(g1y, i11, fmaf(g0y, i01x, -g0x * i01y));
    const float h11x = fmaf(g0x, i11, fmaf(g1x, i01x,  g1y * i01y));
    const float h11y = fmaf(g0y, i11, fmaf(g1y, i01x, -g1x * i01y));
    const float w00  = fmaf(g0x, h00x, g0y * h00y) + fmaf(g1x, h10x, g1y * h10y);
    const float w01x = fmaf(g0x, h01x, g0y * h01y) + fmaf(g1x, h11x, g1y * h11y);
    const float w01y = fmaf(g0x, h01y, -g0y * h01x) + fmaf(g1x, h11y, -g1y * h11x);
    const float w11  = fmaf(g1x, h01x, g1y * h01y) + fmaf(g0x, h11x, g0y * h11y);
    o00  =  gm * w00;
    o11  = -gm * w11;
    o01x = fmaf(gux, w01x, -guy * w01y);
    o01y = fmaf(gux, w01y,  guy * w01x);
}

// Transfer-matrix contraction, SEGMENTED log-depth prefix scan:
// TWO batch elements per warp (16-lane segments, width=16 shuffles),
// 8 warps/CTA -> 32 CTAs x 256 threads, 256 warps total.
//   - lane (seg + k), k<13: ALL wire-k params for its element (5 sincosf)
//   - lane builds its 4x4 transfer matrix L_k; 4-round Kogge-Stone scan
//     within the 16-lane segment -> lane holds P_k = L_k ... L_1
//   - ev[k] = (1,1,2*kappa_{k+1},0) . (P_k . v0);  coalesced stores.
// Math (verified R5-R15):
//   layer-2 M = U2+ Z U2, RZ cancels: m = cos t1 cos t2,
//     mu = -sin t2 - i sin t1 cos t2  (FULL angles t = x*w)
//   layer-1 phi = first column of RZ*RY*RX (half angles)
//   CNOT chain = Gray perm -> nearest-neighbor transfer chain; identity tail
//   telescopes to boundary kappa_{k+1} = 2 Re(conj(phi0) phi1).
__global__ __launch_bounds__(256, 1)
void qsim_tn(const float* __restrict__ x,
             const float* __restrict__ wts,
             float* __restrict__ out,
             int n)
{
    const int W   = blockIdx.x * 8 + (threadIdx.x >> 5);   // warp id
    const int l   = threadIdx.x & 31;
    const int seg = l & 16;                 // 0 or 16
    const int k   = l & 15;                 // wire index within segment
    const int e   = 2 * W + (seg >> 4);     // this segment's batch element
    if (2 * W >= n) return;
    const bool live = (e < n);

    // ---- per-lane params for wire k of element e (R14 layout: all in-lane) ----
    float p0x = 1.f, p0y = 0.f, p1x = 0.f, p1y = 0.f;
    float m = 1.f, mux = 0.f, muy = 0.f, kap = 0.f;

    if (live && k < NQ) {
        const float xv  = __ldg(&x[e * NQ + k]);
        const float wa0 = __ldg(&wts[k * 3 + 0]);
        const float wa1 = __ldg(&wts[k * 3 + 1]);
        const float wa2 = __ldg(&wts[k * 3 + 2]);
        const float wb0 = __ldg(&wts[(NQ + k) * 3 + 0]);
        const float wb1 = __ldg(&wts[(NQ + k) * 3 + 1]);
        float s1, c1, s2, c2, sp, cp, sa, ca, sb, cb;
        __sincosf(0.5f * xv * wa0, &s1, &c1);   // RX half
        __sincosf(0.5f * xv * wa1, &s2, &c2);   // RY half
        __sincosf(0.5f * wa2,      &sp, &cp);   // RZ half
        __sincosf(xv * wb0, &sa, &ca);          // layer-2 full angles
        __sincosf(xv * wb1, &sb, &cb);
        const float A = c2 * c1, B = s2 * s1, C = s2 * c1, D = c2 * s1;
        p0x = fmaf(cp, A,  sp * B);
        p0y = fmaf(cp, B, -sp * A);
        p1x = fmaf(cp, C,  sp * D);
        p1y = fmaf(sp, C, -cp * D);
        m   = ca * cb;
        mux = -sb;
        muy = -sa * cb;
        kap = 2.f * fmaf(p0x, p1x, p0y * p1y);
    }

    // ---- build 4x4 transfer matrix L (P[r*4+c]); k==0 or k>=13: identity ----
    float P[16];
    if (live && k >= 1 && k < NQ) {
        tstep(1.f, 0.f, 0.f, 0.f, p0x, p0y, p1x, p1y, m, mux, muy,
              P[0], P[4], P[8],  P[12]);
        tstep(0.f, 1.f, 0.f, 0.f, p0x, p0y, p1x, p1y, m, mux, muy,
              P[1], P[5], P[9],  P[13]);
        tstep(0.f, 0.f, 1.f, 0.f, p0x, p0y, p1x, p1y, m, mux, muy,
              P[2], P[6], P[10], P[14]);
        tstep(0.f, 0.f, 0.f, 1.f, p0x, p0y, p1x, p1y, m, mux, muy,
              P[3], P[7], P[11], P[15]);
    } else {
        #pragma unroll
        for (int i = 0; i < 16; i++) P[i] = 0.f;
        P[0] = P[5] = P[10] = P[15] = 1.f;
    }

    // ---- segmented Kogge-Stone scan (width=16): P_k <- P_k x P_{k-d} ----
    #pragma unroll
    for (int d = 1; d < 16; d <<= 1) {
        float O[16];
        #pragma unroll
        for (int i = 0; i < 16; i++) O[i] = __shfl_up_sync(FULL, P[i], d, 16);
        if (k >= d) {
            float T[16];
            #pragma unroll
            for (int r = 0; r < 4; r++)
                #pragma unroll
                for (int c = 0; c < 4; c++)
                    T[r * 4 + c] = fmaf(P[r * 4 + 0], O[0 * 4 + c],
                                   fmaf(P[r * 4 + 1], O[1 * 4 + c],
                                   fmaf(P[r * 4 + 2], O[2 * 4 + c],
                                        P[r * 4 + 3] * O[3 * 4 + c])));
            #pragma unroll
            for (int i = 0; i < 16; i++) P[i] = T[i];
        }
    }

    // ---- v0 from wire-0 params (broadcast from segment base lane) ----
    const float q0x = __shfl_sync(FULL, p0x, seg);
    const float q0y = __shfl_sync(FULL, p0y, seg);
    const float q1x = __shfl_sync(FULL, p1x, seg);
    const float q1y = __shfl_sync(FULL, p1y, seg);
    const float qm  = __shfl_sync(FULL, m,   seg);
    const float qux = __shfl_sync(FULL, mux, seg);
    const float quy = __shfl_sync(FULL, muy, seg);
    const float v000  =  qm * fmaf(q0x, q0x, q0y * q0y);
    const float v011  = -qm * fmaf(q1x, q1x, q1y * q1y);
    const float tx    = fmaf(q0x, q1x,  q0y * q1y);
    const float ty    = fmaf(q0x, q1y, -q0y * q1x);
    const float v001x = fmaf(qux, tx, -quy * ty);
    const float v001y = fmaf(qux, ty,  quy * tx);

    // ---- v_k = P_k . v0 (rows 0,1,2 needed) ----
    const float r00  = fmaf(P[0],  v000, fmaf(P[1],  v011, fmaf(P[2],  v001x, P[3]  * v001y)));
    const float r11  = fmaf(P[4],  v000, fmaf(P[5],  v011, fmaf(P[6],  v001x, P[7]  * v001y)));
    const float r01x = fmaf(P[8],  v000, fmaf(P[9],  v011, fmaf(P[10], v001x, P[11] * v001y)));

    // ---- ev[k] = v00+v11 + kappa_{k+1} * 2*v01x  (k==12: kappa=1) ----
    const float knext = __shfl_sync(FULL, kap, seg + ((k + 1) & 15));
    const float gk = (k == NQ - 1) ? 1.f : knext;
    const float ev = r00 + r11 + gk * (2.f * r01x);

    if (live && k < NQ) out[e * NQ + k] = ev;
}

extern "C" void kernel_launch(void* const* d_in, const int* in_sizes, int n_in,
                              void* d_out, int out_size)
{
    const float* x = (const float*)d_in[0];   // (B, 13) float32
    const float* w = (const float*)d_in[1];   // (2, 13, 3) float32
    float* out     = (float*)d_out;           // (B, 13) float32

    const int B = in_sizes[0] / NQ;           // 512
    const int warps  = (B + 1) / 2;           // 256 warps (2 elems/warp)
    const int blocks = (warps + 7) / 8;       // 32 CTAs x 256 threads
    qsim_tn<<<blocks, 256>>>(x, w, out, B);
}

// round 17
// speedup vs baseline: 1.0386x; 1.0386x over previous
#include <cuda_runtime.h>

#define NQ 13
#define FULL 0xffffffffu

// One transfer step (verified R5-R16): v_new = L(v) given wire params.
__device__ __forceinline__ void tstep(
    float i00, float i11, float i01x, float i01y,
    float g0x, float g0y, float g1x, float g1y,
    float gm, float gux, float guy,
    float& o00, float& o11, float& o01x, float& o01y)
{
    const float h00x = fmaf(g0x, i00, fmaf(g1x, i01x, -g1y * i01y));
    const float h00y = fmaf(g0y, i00, fmaf(g1x, i01y,  g1y * i01x));
    const float h01x = fmaf(g1x, i00, fmaf(g0x, i01x, -g0y * i01y));
    const float h01y = fmaf(g1y, i00, fmaf(g0x, i01y,  g0y * i01x));
    const float h10x = fmaf(g1x, i11, fmaf(g0x, i01x,  g0y * i01y));
    const float h10y = fmaf(g1y, i11, fmaf(g0y, i01x, -g0x * i01y));
    const float h11x = fmaf(g0x, i11, fmaf(g1x, i01x,  g1y * i01y));
    const float h11y = fmaf(g0y, i11, fmaf(g1y, i01x, -g1x * i01y));
    const float w00  = fmaf(g0x, h00x, g0y * h00y) + fmaf(g1x, h10x, g1y * h10y);
    const float w01x = fmaf(g0x, h01x, g0y * h01y) + fmaf(g1x, h11x, g1y * h11y);
    const float w01y = fmaf(g0x, h01y, -g0y * h01x) + fmaf(g1x, h11y, -g1y * h11x);
    const float w11  = fmaf(g1x, h01x, g1y * h01y) + fmaf(g0x, h11x, g0y * h11y);
    o00  =  gm * w00;
    o11  = -gm * w11;
    o01x = fmaf(gux, w01x, -guy * w01y);
    o01y = fmaf(gux, w01y,  guy * w01x);
}

// Transfer-matrix contraction with LOG-DEPTH prefix scan (terminal form).
// One warp per element, 8 warps/CTA (64 CTAs x 256 threads).
//   - lane l (l<13) computes ALL wire-l params (5 independent sincosf)
//   - lane l builds its 4x4 transfer matrix L_l from the step body applied
//     to the 4 basis vectors
//   - Kogge-Stone scan (4 rounds) -> lane l holds P_l = L_l ... L_1
//   - ev[l] = (1,1,2*kappa_{l+1},0) . (P_l . v0);  one coalesced store.
// Math:
//   layer-2 M = U2+ Z U2, RZ cancels: m = cos t1 cos t2,
//     mu = -sin t2 - i sin t1 cos t2  (FULL angles t = x*w)
//   layer-1 phi = first column of RZ*RY*RX (half angles)
//   CNOT chain = Gray perm -> nearest-neighbor transfer chain; identity tail
//   telescopes to boundary kappa_{l+1} = 2 Re(conj(phi0) phi1).
__global__ __launch_bounds__(256, 1)
void qsim_tn(const float* __restrict__ x,
             const float* __restrict__ wts,
             float* __restrict__ out,
             int n)
{
    const int e = blockIdx.x * 8 + (threadIdx.x >> 5);
    const int l = threadIdx.x & 31;
    if (e >= n) return;

    // ---- per-lane params for wire l ----
    float p0x = 1.f, p0y = 0.f, p1x = 0.f, p1y = 0.f;
    float m = 1.f, mux = 0.f, muy = 0.f, kap = 0.f;

    if (l < NQ) {
        const float xv = __ldg(&x[e * NQ + l]);
        const float wa0 = __ldg(&wts[l * 3 + 0]);
        const float wa1 = __ldg(&wts[l * 3 + 1]);
        const float wa2 = __ldg(&wts[l * 3 + 2]);
        const float wb0 = __ldg(&wts[(NQ + l) * 3 + 0]);
        const float wb1 = __ldg(&wts[(NQ + l) * 3 + 1]);
        float s1, c1, s2, c2, sp, cp, sa, ca, sb, cb;
        __sincosf(0.5f * xv * wa0, &s1, &c1);   // RX half
        __sincosf(0.5f * xv * wa1, &s2, &c2);   // RY half
        __sincosf(0.5f * wa2,      &sp, &cp);   // RZ half
        __sincosf(xv * wb0, &sa, &ca);          // layer-2 full angles
        __sincosf(xv * wb1, &sb, &cb);
        const float A = c2 * c1, B = s2 * s1, C = s2 * c1, D = c2 * s1;
        p0x = fmaf(cp, A,  sp * B);
        p0y = fmaf(cp, B, -sp * A);
        p1x = fmaf(cp, C,  sp * D);
        p1y = fmaf(sp, C, -cp * D);
        m   = ca * cb;
        mux = -sb;
        muy = -sa * cb;
        kap = 2.f * fmaf(p0x, p1x, p0y * p1y);
    }

    // ---- build 4x4 transfer matrix L (P[r*4+c]); lane 0 & lanes>=13: I ----
    float P[16];
    if (l >= 1 && l < NQ) {
        tstep(1.f, 0.f, 0.f, 0.f, p0x, p0y, p1x, p1y, m, mux, muy,
              P[0], P[4], P[8],  P[12]);
        tstep(0.f, 1.f, 0.f, 0.f, p0x, p0y, p1x, p1y, m, mux, muy,
              P[1], P[5], P[9],  P[13]);
        tstep(0.f, 0.f, 1.f, 0.f, p0x, p0y, p1x, p1y, m, mux, muy,
              P[2], P[6], P[10], P[14]);
        tstep(0.f, 0.f, 0.f, 1.f, p0x, p0y, p1x, p1y, m, mux, muy,
              P[3], P[7], P[11], P[15]);
    } else {
        #pragma unroll
        for (int i = 0; i < 16; i++) P[i] = 0.f;
        P[0] = P[5] = P[10] = P[15] = 1.f;
    }

    // ---- Kogge-Stone inclusive scan: P_l <- P_l x P_{l-d} ----
    #pragma unroll
    for (int d = 1; d < 16; d <<= 1) {
        float O[16];
        #pragma unroll
        for (int i = 0; i < 16; i++) O[i] = __shfl_up_sync(FULL, P[i], d);
        if (l >= d) {
            float T[16];
            #pragma unroll
            for (int r = 0; r < 4; r++)
                #pragma unroll
                for (int c = 0; c < 4; c++)
                    T[r * 4 + c] = fmaf(P[r * 4 + 0], O[0 * 4 + c],
                                   fmaf(P[r * 4 + 1], O[1 * 4 + c],
                                   fmaf(P[r * 4 + 2], O[2 * 4 + c],
                                        P[r * 4 + 3] * O[3 * 4 + c])));
            #pragma unroll
            for (int i = 0; i < 16; i++) P[i] = T[i];
        }
    }

    // ---- v0 from wire-0 params (broadcast from lane 0) ----
    const float q0x = __shfl_sync(FULL, p0x, 0);
    const float q0y = __shfl_sync(FULL, p0y, 0);
    const float q1x = __shfl_sync(FULL, p1x, 0);
    const float q1y = __shfl_sync(FULL, p1y, 0);
    const float qm  = __shfl_sync(FULL, m,   0);
    const float qux = __shfl_sync(FULL, mux, 0);
    const float quy = __shfl_sync(FULL, muy, 0);
    const float v000  =  qm * fmaf(q0x, q0x, q0y * q0y);
    const float v011  = -qm * fmaf(q1x, q1x, q1y * q1y);
    const float tx    = fmaf(q0x, q1x,  q0y * q1y);
    const float ty    = fmaf(q0x, q1y, -q0y * q1x);
    const float v001x = fmaf(qux, tx, -quy * ty);
    const float v001y = fmaf(qux, ty,  quy * tx);

    // ---- v_l = P_l . v0 (rows 0,1,2 needed) ----
    const float r00  = fmaf(P[0],  v000, fmaf(P[1],  v011, fmaf(P[2],  v001x, P[3]  * v001y)));
    const float r11  = fmaf(P[4],  v000, fmaf(P[5],  v011, fmaf(P[6],  v001x, P[7]  * v001y)));
    const float r01x = fmaf(P[8],  v000, fmaf(P[9],  v011, fmaf(P[10], v001x, P[11] * v001y)));

    // ---- ev[l] = v00+v11 + kappa_{l+1} * 2*v01x  (lane 12: kappa=1) ----
    const float knext = __shfl_sync(FULL, kap, (l + 1) & 31);
    const float gk = (l == NQ - 1) ? 1.f : knext;
    const float ev = r00 + r11 + gk * (2.f * r01x);

    if (l < NQ) out[e * NQ + l] = ev;
}

extern "C" void kernel_launch(void* const* d_in, const int* in_sizes, int n_in,
                              void* d_out, int out_size)
{
    const float* x = (const float*)d_in[0];   // (B, 13) float32
    const float* w = (const float*)d_in[1];   // (2, 13, 3) float32
    float* out     = (float*)d_out;           // (B, 13) float32

    const int B = in_sizes[0] / NQ;           // 512
    const int blocks = (B + 7) / 8;           // 64 CTAs x 256 threads
    qsim_tn<<<blocks, 256>>>(x, w, out, B);
}